// round 13
// baseline (speedup 1.0000x reference)
#include <cuda_runtime.h>
#include <cuda_fp16.h>

#define NS 3
#define NQ 64
#define NN (128*128*32)    // 524288
#define NN4 (NN/4)         // 131072 float4 per row
#define NW (NN/32)         // 16384 packed words per row
#define NC 21
#define IOU_T 0.2f
#define WCH 256
#define SROW (WCH+4)       // 260-word smem row stride

// ---------------- scratch (device globals; no allocation) ----------------
__device__ unsigned g_mask [NS*NQ*NW];
__device__ unsigned g_mask2[NQ*NW];
__device__ unsigned g_occ  [NW];
__device__ uint2    g_a1   [(size_t)NQ*NN4];   // merged anchor after iter1, fp16x4 (output path only)
__device__ int g_cnt [NS*NQ];
__device__ int g_cnt2[NQ];
__device__ int g_inter1[NQ*NQ];
__device__ int g_inter2[NQ*NQ];

__device__ __forceinline__ float sigf(float x){ return 1.0f/(1.0f + __expf(-x)); }

__device__ __forceinline__ uint2 pack4h(float a, float b, float c, float d){
    __half2 h01 = __floats2half2_rn(a, b);
    __half2 h23 = __floats2half2_rn(c, d);
    uint2 r; r.x = *(unsigned*)&h01; r.y = *(unsigned*)&h23; return r;
}
__device__ __forceinline__ float4 unpack4h(uint2 hv){
    float2 a01 = __half22float2(*(__half2*)&hv.x);
    float2 a23 = __half22float2(*(__half2*)&hv.y);
    return make_float4(a01.x, a01.y, a23.x, a23.y);
}

// warp-wide argmax of IoU row q (identical arithmetic/tie-break to the old match kernel)
// returns same (best,bi) on all 32 lanes
__device__ __forceinline__ void warp_match(const int* __restrict__ inter,
                                           const int* __restrict__ cb,
                                           int ca_i, int q, float& best, int& bi){
    int lane = threadIdx.x & 31;
    float ca = (float)ca_i;
    best = -1.0f; bi = 0;
    #pragma unroll
    for (int k = 0; k < 2; k++){
        int p = lane + k*32;
        float in = (float)inter[q*NQ + p];
        float un = ca + (float)cb[p] - in;
        float io = in / fmaxf(un, 1.0f);
        if (io > best){ best = io; bi = p; }
    }
    #pragma unroll
    for (int d = 16; d; d >>= 1){
        float ob = __shfl_xor_sync(~0u, best, d);
        int   oi = __shfl_xor_sync(~0u, bi,   d);
        if (ob > best || (ob == best && oi < bi)){ best = ob; bi = oi; }
    }
}

// ---------------- zero accumulators ----------------
__global__ void init_kernel(){
    int t = blockIdx.x*256 + threadIdx.x;
    if (t < NQ*NQ){ g_inter1[t] = 0; g_inter2[t] = 0; }
    if (t < NS*NQ) g_cnt[t] = 0;
    if (t < NQ)    g_cnt2[t] = 0;
}

// ---------------- occupancy bits (pure streaming) ----------------
__global__ void occ_kernel(const float4* __restrict__ sem4){
    int f = blockIdx.x*256 + threadIdx.x;
    int lane = threadIdx.x & 31;
    float4 v0 = __ldcs(&sem4[f]);
    unsigned nib = 0;
    #pragma unroll
    for (int c = 1; c < NC; c++){
        float4 vc = __ldcs(&sem4[(size_t)c*NN4 + f]);
        nib |= (unsigned)(vc.x > v0.x) | ((unsigned)(vc.y > v0.y) << 1)
             | ((unsigned)(vc.z > v0.z) << 2) | ((unsigned)(vc.w > v0.w) << 3);
    }
    unsigned part = nib << ((lane & 7) * 4);
    part |= __shfl_xor_sync(~0u, part, 1);
    part |= __shfl_xor_sync(~0u, part, 2);
    part |= __shfl_xor_sync(~0u, part, 4);
    if ((lane & 7) == 0) g_occ[f >> 3] = part;
}

// ---------------- pass 1: pack (logit>0) bits — pure stream ----------------
__global__ void mask_kernel(const float4* __restrict__ vl4, int s_base){
    int s = blockIdx.z + s_base, q = blockIdx.y;
    int row = s*NQ + q;
    size_t row4 = (size_t)row * NN4;
    size_t mrow = (size_t)row * NW;
    int t = threadIdx.x, lane = t & 31;
    #pragma unroll
    for (int j = 0; j < 4; j++){
        int f = blockIdx.x*1024 + j*256 + t;
        float4 v = __ldcs(&vl4[row4 + f]);
        unsigned nib = (unsigned)(v.x > 0.f) | ((unsigned)(v.y > 0.f) << 1)
                     | ((unsigned)(v.z > 0.f) << 2) | ((unsigned)(v.w > 0.f) << 3);
        unsigned part = nib << ((lane & 7) * 4);
        part |= __shfl_xor_sync(~0u, part, 1);
        part |= __shfl_xor_sync(~0u, part, 2);
        part |= __shfl_xor_sync(~0u, part, 4);
        if ((lane & 7) == 0) g_mask[mrow + (f >> 3)] = part;
    }
}

// ---------------- bit-popcount GEMM + fused row counts (R6 body; 3 blocks/SM) ----------------
__global__ void __launch_bounds__(256, 3) inter_kernel(int round){
    __shared__ unsigned sA[16*SROW];
    __shared__ unsigned sB[16*SROW];
    const unsigned* A = round ? g_mask2 : g_mask;
    const unsigned* B = g_mask + (size_t)(round ? 2 : 1) * NQ * NW;
    int* inter = round ? g_inter2 : g_inter1;
    int* cntA  = round ? g_cnt2 : g_cnt;
    int* cntB  = g_cnt + (round ? 2 : 1) * NQ;
    int w0 = blockIdx.x * WCH;
    int q0 = blockIdx.y * 16, p0 = blockIdx.z * 16;
    int t = threadIdx.x;
    for (int i = t; i < 16*64; i += 256){
        int r = i >> 6, c = (i & 63) * 4;
        *(uint4*)&sA[r*SROW + c] = *(const uint4*)&A[(size_t)(q0 + r)*NW + w0 + c];
        *(uint4*)&sB[r*SROW + c] = *(const uint4*)&B[(size_t)(p0 + r)*NW + w0 + c];
    }
    __syncthreads();
    if (blockIdx.z == 0){
        int r = t >> 4, part = t & 15;
        int c = 0;
        #pragma unroll
        for (int w = 0; w < 16; w++) c += __popc(sA[r*SROW + part*16 + w]);
        #pragma unroll
        for (int d = 8; d; d >>= 1) c += __shfl_down_sync(~0u, c, d, 16);
        if (part == 0) atomicAdd(&cntA[q0 + r], c);
    }
    if (blockIdx.y == 0){
        int r = t >> 4, part = t & 15;
        int c = 0;
        #pragma unroll
        for (int w = 0; w < 16; w++) c += __popc(sB[r*SROW + part*16 + w]);
        #pragma unroll
        for (int d = 8; d; d >>= 1) c += __shfl_down_sync(~0u, c, d, 16);
        if (part == 0) atomicAdd(&cntB[p0 + r], c);
    }
    int px = t & 3, qx = (t >> 2) & 3, ws = t >> 4;
    int acc[16];
    #pragma unroll
    for (int k = 0; k < 16; k++) acc[k] = 0;
    int wbeg = ws * 16;
    #pragma unroll
    for (int w = wbeg; w < wbeg + 16; w += 4){
        uint4 a[4], b[4];
        #pragma unroll
        for (int i = 0; i < 4; i++){
            a[i] = *(uint4*)&sA[(qx + 4*i)*SROW + w];
            b[i] = *(uint4*)&sB[(px + 4*i)*SROW + w];
        }
        #pragma unroll
        for (int i = 0; i < 4; i++)
            #pragma unroll
            for (int j = 0; j < 4; j++)
                acc[i*4+j] += __popc(a[i].x & b[j].x) + __popc(a[i].y & b[j].y)
                            + __popc(a[i].z & b[j].z) + __popc(a[i].w & b[j].w);
    }
    __syncthreads();
    int* sRed = (int*)sA;
    #pragma unroll
    for (int i = 0; i < 4; i++)
        #pragma unroll
        for (int j = 0; j < 4; j++)
            sRed[ws*256 + (qx + 4*i)*16 + (px + 4*j)] = acc[i*4+j];
    __syncthreads();
    int s = 0;
    #pragma unroll
    for (int k = 0; k < 16; k++) s += sRed[k*256 + t];
    atomicAdd(&inter[(q0 + (t >> 4))*NQ + p0 + (t & 15)], s);
}

// ---------------- pass 2: inline match0 + merged anchor (fp32-exact bits) + fp16 a1 ----------------
__global__ void mask2_kernel(const float4* __restrict__ vl4){
    __shared__ int s_p, s_m;
    int q = blockIdx.y;
    int t = threadIdx.x, lane = t & 31;
    if (t < 32){
        float best; int bi;
        warp_match(g_inter1, g_cnt + NQ, g_cnt[q], q, best, bi);
        if (lane == 0){ s_p = bi; s_m = best > IOU_T; }
    }
    __syncthreads();
    int p = s_p, m = s_m;
    size_t r0 = (size_t)q * NN4;
    size_t r1 = (size_t)(NQ + p) * NN4;
    #pragma unroll
    for (int j = 0; j < 4; j++){
        int f = blockIdx.x*1024 + j*256 + t;
        float4 v0 = __ldcs(&vl4[r0 + f]);
        float4 a;
        a.x = sigf(v0.x); a.y = sigf(v0.y); a.z = sigf(v0.z); a.w = sigf(v0.w);
        if (m){
            float4 v1 = __ldcs(&vl4[r1 + f]);
            a.x = (a.x + sigf(v1.x)) * 0.5f;
            a.y = (a.y + sigf(v1.y)) * 0.5f;
            a.z = (a.z + sigf(v1.z)) * 0.5f;
            a.w = (a.w + sigf(v1.w)) * 0.5f;
        }
        g_a1[(size_t)q*NN4 + f] = pack4h(a.x, a.y, a.z, a.w);
        unsigned nib = (unsigned)(a.x > 0.5f) | ((unsigned)(a.y > 0.5f) << 1)
                     | ((unsigned)(a.z > 0.5f) << 2) | ((unsigned)(a.w > 0.5f) << 3);
        unsigned part = nib << ((lane & 7) * 4);
        part |= __shfl_xor_sync(~0u, part, 1);
        part |= __shfl_xor_sync(~0u, part, 2);
        part |= __shfl_xor_sync(~0u, part, 4);
        if ((lane & 7) == 0) g_mask2[(size_t)q*NW + (f >> 3)] = part;
    }
}

// ---------------- pass 3: inline match0+match1+keep, then final output ----------------
__global__ void out_kernel(const float4* __restrict__ vl4, float4* __restrict__ out4){
    __shared__ int s_keep, s_m2, s_idx2;
    int q = blockIdx.y;
    int t = threadIdx.x;
    if (t < 32){
        float b1, b2; int i1, i2;
        warp_match(g_inter1, g_cnt + NQ,   g_cnt[q],  q, b1, i1);
        warp_match(g_inter2, g_cnt + 2*NQ, g_cnt2[q], q, b2, i2);
        if ((t & 31) == 0){
            s_idx2 = i2;
            s_m2   = b2 > IOU_T;
            s_keep = ((b1 + b2) * 0.5f) > IOU_T;
        }
    }
    __syncthreads();
    int keep = s_keep, m2 = s_m2;
    size_t orow4 = (size_t)q * NN4;
    size_t r2 = (size_t)(2*NQ + s_idx2) * NN4;
    #pragma unroll
    for (int j = 0; j < 4; j++){
        int f = blockIdx.x*1024 + j*256 + t;
        float4 o = make_float4(0.f, 0.f, 0.f, 0.f);
        if (keep){
            float4 a = unpack4h(g_a1[(size_t)q*NN4 + f]);   // mostly L2-hit
            if (m2){
                float4 v2 = __ldcs(&vl4[r2 + f]);
                a.x = (a.x*2.f + sigf(v2.x)) * (1.f/3.f);
                a.y = (a.y*2.f + sigf(v2.y)) * (1.f/3.f);
                a.z = (a.z*2.f + sigf(v2.z)) * (1.f/3.f);
                a.w = (a.w*2.f + sigf(v2.w)) * (1.f/3.f);
            }
            unsigned ob = g_occ[f >> 3] >> ((f & 7) * 4);
            o.x = (ob & 1u) ? a.x : 0.f;
            o.y = (ob & 2u) ? a.y : 0.f;
            o.z = (ob & 4u) ? a.z : 0.f;
            o.w = (ob & 8u) ? a.w : 0.f;
        }
        __stcs(&out4[orow4 + f], o);
    }
}

// ---------------- launch: R11 schedule minus match launches, init off-path ----------------
extern "C" void kernel_launch(void* const* d_in, const int* in_sizes, int n_in,
                              void* d_out, int out_size){
    const float4* vl4  = (const float4*)d_in[0];   // voxel_logits [3,64,128,128,32]
    const float4* sem4 = (const float4*)d_in[2];   // sem_prob_dense [21,128,128,32]
    float4* out4 = (float4*)d_out;                 // [64,128,128,32]

    static cudaStream_t s1 = 0;
    static cudaEvent_t evF = 0, evA = 0, evI0 = 0, evM2 = 0, evI1 = 0;
    static int initd = 0;
    if (!initd){
        if (cudaStreamCreateWithFlags(&s1, cudaStreamNonBlocking) != cudaSuccess) s1 = 0;
        cudaEventCreateWithFlags(&evF,  cudaEventDisableTiming);
        cudaEventCreateWithFlags(&evA,  cudaEventDisableTiming);
        cudaEventCreateWithFlags(&evI0, cudaEventDisableTiming);
        cudaEventCreateWithFlags(&evM2, cudaEventDisableTiming);
        cudaEventCreateWithFlags(&evI1, cudaEventDisableTiming);
        initd = 1;
    }

    if (s1){
        // S1: init (zeros feed only inter0/inter1 atomics, which run on S1)
        cudaEventRecord(evF, 0);
        cudaStreamWaitEvent(s1, evF, 0);
        init_kernel <<< 16, 256, 0, s1 >>> ();

        // S0: mask01 (s=0,1) — inter0's inputs
        mask_kernel <<< dim3(NN4/1024, NQ, 2), 256 >>> (vl4, 0);
        cudaEventRecord(evA, 0);

        // S1: inter0 concurrent with S0's mask_s2
        cudaStreamWaitEvent(s1, evA, 0);
        inter_kernel<<< dim3(NW/WCH, 4, 4), 256, 0, s1 >>> (0);
        cudaEventRecord(evI0, s1);

        // S0: mask s=2 (DRAM work under inter0's ALU window)
        mask_kernel <<< dim3(NN4/1024, NQ, 1), 256 >>> (vl4, 2);

        // S0: mask2 (match0 inlined in its head)
        cudaStreamWaitEvent(0, evI0, 0);
        mask2_kernel<<< dim3(NN4/1024, NQ), 256 >>> (vl4);
        cudaEventRecord(evM2, 0);

        // S1: inter1 concurrent with S0's occ
        cudaStreamWaitEvent(s1, evM2, 0);
        inter_kernel<<< dim3(NW/WCH, 4, 4), 256, 0, s1 >>> (1);
        cudaEventRecord(evI1, s1);

        // S0: occ (DRAM work under inter1's ALU window)
        occ_kernel  <<< NN4/256, 256 >>> (sem4);

        // S0: out (match0+match1+keep inlined in its head)
        cudaStreamWaitEvent(0, evI1, 0);
        out_kernel  <<< dim3(NN4/1024, NQ), 256 >>> (vl4, out4);
    } else {
        init_kernel <<< 16, 256 >>> ();
        mask_kernel <<< dim3(NN4/1024, NQ, 3), 256 >>> (vl4, 0);
        occ_kernel  <<< NN4/256, 256 >>> (sem4);
        inter_kernel<<< dim3(NW/WCH, 4, 4), 256 >>> (0);
        mask2_kernel<<< dim3(NN4/1024, NQ), 256 >>> (vl4);
        inter_kernel<<< dim3(NW/WCH, 4, 4), 256 >>> (1);
        out_kernel  <<< dim3(NN4/1024, NQ), 256 >>> (vl4, out4);
    }
}

// round 14
// speedup vs baseline: 1.0664x; 1.0664x over previous
#include <cuda_runtime.h>
#include <cuda_fp16.h>

#define NS 3
#define NQ 64
#define NN (128*128*32)    // 524288
#define NN4 (NN/4)         // 131072 float4 per row
#define NW (NN/32)         // 16384 packed words per row
#define NC 21
#define IOU_T 0.2f
#define WCH 256
#define SROW (WCH+4)       // 260-word smem row stride

// ---------------- scratch (device globals; no allocation) ----------------
__device__ unsigned g_mask [NS*NQ*NW];
__device__ unsigned g_mask2[NQ*NW];
__device__ unsigned g_occ  [NW];
__device__ uint2    g_a1   [(size_t)NQ*NN4];   // merged anchor after iter1, fp16x4 (output path only)
__device__ uint2    g_sig2 [(size_t)NQ*NN4];   // sigmoid(l2), fp16x4 (output path only)
__device__ int g_cnt [NS*NQ];
__device__ int g_cnt2[NQ];
__device__ int g_inter1[NQ*NQ];
__device__ int g_inter2[NQ*NQ];
__device__ int g_idx1[NQ], g_m1[NQ], g_idx2[NQ], g_m2[NQ], g_keep[NQ];
__device__ float g_iou1[NQ];

__device__ __forceinline__ float sigf(float x){ return 1.0f/(1.0f + __expf(-x)); }

__device__ __forceinline__ uint2 pack4h(float a, float b, float c, float d){
    __half2 h01 = __floats2half2_rn(a, b);
    __half2 h23 = __floats2half2_rn(c, d);
    uint2 r; r.x = *(unsigned*)&h01; r.y = *(unsigned*)&h23; return r;
}
__device__ __forceinline__ float4 unpack4h(uint2 hv){
    float2 a01 = __half22float2(*(__half2*)&hv.x);
    float2 a23 = __half22float2(*(__half2*)&hv.y);
    return make_float4(a01.x, a01.y, a23.x, a23.y);
}

// ---------------- zero accumulators ----------------
__global__ void init_kernel(){
    int t = blockIdx.x*256 + threadIdx.x;
    if (t < NQ*NQ){ g_inter1[t] = 0; g_inter2[t] = 0; }
    if (t < NS*NQ) g_cnt[t] = 0;
    if (t < NQ)    g_cnt2[t] = 0;
}

// ---------------- occupancy bits (pure streaming) ----------------
__global__ void occ_kernel(const float4* __restrict__ sem4){
    int f = blockIdx.x*256 + threadIdx.x;
    int lane = threadIdx.x & 31;
    float4 v0 = __ldcs(&sem4[f]);
    unsigned nib = 0;
    #pragma unroll
    for (int c = 1; c < NC; c++){
        float4 vc = __ldcs(&sem4[(size_t)c*NN4 + f]);
        nib |= (unsigned)(vc.x > v0.x) | ((unsigned)(vc.y > v0.y) << 1)
             | ((unsigned)(vc.z > v0.z) << 2) | ((unsigned)(vc.w > v0.w) << 3);
    }
    unsigned part = nib << ((lane & 7) * 4);
    part |= __shfl_xor_sync(~0u, part, 1);
    part |= __shfl_xor_sync(~0u, part, 2);
    part |= __shfl_xor_sync(~0u, part, 4);
    if ((lane & 7) == 0) g_occ[f >> 3] = part;
}

// ---------------- pass 1: pack (logit>0) bits, s=0,1 — pure stream ----------------
__global__ void mask_kernel(const float4* __restrict__ vl4){
    int s = blockIdx.z, q = blockIdx.y;
    int row = s*NQ + q;
    size_t row4 = (size_t)row * NN4;
    size_t mrow = (size_t)row * NW;
    int t = threadIdx.x, lane = t & 31;
    #pragma unroll
    for (int j = 0; j < 4; j++){
        int f = blockIdx.x*1024 + j*256 + t;
        float4 v = __ldcs(&vl4[row4 + f]);
        unsigned nib = (unsigned)(v.x > 0.f) | ((unsigned)(v.y > 0.f) << 1)
                     | ((unsigned)(v.z > 0.f) << 2) | ((unsigned)(v.w > 0.f) << 3);
        unsigned part = nib << ((lane & 7) * 4);
        part |= __shfl_xor_sync(~0u, part, 1);
        part |= __shfl_xor_sync(~0u, part, 2);
        part |= __shfl_xor_sync(~0u, part, 4);
        if ((lane & 7) == 0) g_mask[mrow + (f >> 3)] = part;
    }
}

// ---------------- pass 1b (s=2): bits + sigmoid(l2) fp16 cache ----------------
__global__ void mask_s2_kernel(const float4* __restrict__ vl4){
    int q = blockIdx.y;
    int row = 2*NQ + q;
    size_t row4 = (size_t)row * NN4;
    size_t mrow = (size_t)row * NW;
    int t = threadIdx.x, lane = t & 31;
    #pragma unroll
    for (int j = 0; j < 4; j++){
        int f = blockIdx.x*1024 + j*256 + t;
        float4 v = __ldcs(&vl4[row4 + f]);
        g_sig2[(size_t)q*NN4 + f] = pack4h(sigf(v.x), sigf(v.y), sigf(v.z), sigf(v.w));
        unsigned nib = (unsigned)(v.x > 0.f) | ((unsigned)(v.y > 0.f) << 1)
                     | ((unsigned)(v.z > 0.f) << 2) | ((unsigned)(v.w > 0.f) << 3);
        unsigned part = nib << ((lane & 7) * 4);
        part |= __shfl_xor_sync(~0u, part, 1);
        part |= __shfl_xor_sync(~0u, part, 2);
        part |= __shfl_xor_sync(~0u, part, 4);
        if ((lane & 7) == 0) g_mask[mrow + (f >> 3)] = part;
    }
}

// ---------------- bit-popcount GEMM + fused row counts (R6 body; 3 blocks/SM) ----------------
__global__ void __launch_bounds__(256, 3) inter_kernel(int round){
    __shared__ unsigned sA[16*SROW];
    __shared__ unsigned sB[16*SROW];
    const unsigned* A = round ? g_mask2 : g_mask;
    const unsigned* B = g_mask + (size_t)(round ? 2 : 1) * NQ * NW;
    int* inter = round ? g_inter2 : g_inter1;
    int* cntA  = round ? g_cnt2 : g_cnt;
    int* cntB  = g_cnt + (round ? 2 : 1) * NQ;
    int w0 = blockIdx.x * WCH;
    int q0 = blockIdx.y * 16, p0 = blockIdx.z * 16;
    int t = threadIdx.x;
    for (int i = t; i < 16*64; i += 256){
        int r = i >> 6, c = (i & 63) * 4;
        *(uint4*)&sA[r*SROW + c] = *(const uint4*)&A[(size_t)(q0 + r)*NW + w0 + c];
        *(uint4*)&sB[r*SROW + c] = *(const uint4*)&B[(size_t)(p0 + r)*NW + w0 + c];
    }
    __syncthreads();
    if (blockIdx.z == 0){
        int r = t >> 4, part = t & 15;
        int c = 0;
        #pragma unroll
        for (int w = 0; w < 16; w++) c += __popc(sA[r*SROW + part*16 + w]);
        #pragma unroll
        for (int d = 8; d; d >>= 1) c += __shfl_down_sync(~0u, c, d, 16);
        if (part == 0) atomicAdd(&cntA[q0 + r], c);
    }
    if (blockIdx.y == 0){
        int r = t >> 4, part = t & 15;
        int c = 0;
        #pragma unroll
        for (int w = 0; w < 16; w++) c += __popc(sB[r*SROW + part*16 + w]);
        #pragma unroll
        for (int d = 8; d; d >>= 1) c += __shfl_down_sync(~0u, c, d, 16);
        if (part == 0) atomicAdd(&cntB[p0 + r], c);
    }
    int px = t & 3, qx = (t >> 2) & 3, ws = t >> 4;
    int acc[16];
    #pragma unroll
    for (int k = 0; k < 16; k++) acc[k] = 0;
    int wbeg = ws * 16;
    #pragma unroll
    for (int w = wbeg; w < wbeg + 16; w += 4){
        uint4 a[4], b[4];
        #pragma unroll
        for (int i = 0; i < 4; i++){
            a[i] = *(uint4*)&sA[(qx + 4*i)*SROW + w];
            b[i] = *(uint4*)&sB[(px + 4*i)*SROW + w];
        }
        #pragma unroll
        for (int i = 0; i < 4; i++)
            #pragma unroll
            for (int j = 0; j < 4; j++)
                acc[i*4+j] += __popc(a[i].x & b[j].x) + __popc(a[i].y & b[j].y)
                            + __popc(a[i].z & b[j].z) + __popc(a[i].w & b[j].w);
    }
    __syncthreads();
    int* sRed = (int*)sA;
    #pragma unroll
    for (int i = 0; i < 4; i++)
        #pragma unroll
        for (int j = 0; j < 4; j++)
            sRed[ws*256 + (qx + 4*i)*16 + (px + 4*j)] = acc[i*4+j];
    __syncthreads();
    int s = 0;
    #pragma unroll
    for (int k = 0; k < 16; k++) s += sRed[k*256 + t];
    atomicAdd(&inter[(q0 + (t >> 4))*NQ + p0 + (t & 15)], s);
}

// ---------------- parallel argmax: one warp per q (first-index tie-break) ----------------
__global__ void match_kernel(int round){
    int q = blockIdx.x*8 + (threadIdx.x >> 5);
    int lane = threadIdx.x & 31;
    const int* inter = round ? g_inter2 : g_inter1;
    const int* cb    = g_cnt + (round ? 2*NQ : NQ);
    float ca = (float)(round ? g_cnt2[q] : g_cnt[q]);
    float best = -1.0f; int bi = 0;
    #pragma unroll
    for (int k = 0; k < 2; k++){
        int p = lane + k*32;
        float in = (float)inter[q*NQ + p];
        float un = ca + (float)cb[p] - in;
        float io = in / fmaxf(un, 1.0f);
        if (io > best){ best = io; bi = p; }
    }
    #pragma unroll
    for (int d = 16; d; d >>= 1){
        float ob = __shfl_xor_sync(~0u, best, d);
        int   oi = __shfl_xor_sync(~0u, bi,   d);
        if (ob > best || (ob == best && oi < bi)){ best = ob; bi = oi; }
    }
    if (lane == 0){
        if (round == 0){
            g_idx1[q] = bi; g_m1[q] = best > IOU_T; g_iou1[q] = best;
        } else {
            g_idx2[q] = bi; g_m2[q] = best > IOU_T;
            g_keep[q] = ((g_iou1[q] + best) * 0.5f) > IOU_T;
        }
    }
}

// ---------------- pass 2: merged anchor (fp32-exact bits) + fp16 a1 ----------------
__global__ void mask2_kernel(const float4* __restrict__ vl4){
    int q = blockIdx.y;
    int t = threadIdx.x, lane = t & 31;
    int p = g_idx1[q], m = g_m1[q];
    size_t r0 = (size_t)q * NN4;
    size_t r1 = (size_t)(NQ + p) * NN4;
    #pragma unroll
    for (int j = 0; j < 4; j++){
        int f = blockIdx.x*1024 + j*256 + t;
        float4 v0 = __ldcs(&vl4[r0 + f]);
        float4 a;
        a.x = sigf(v0.x); a.y = sigf(v0.y); a.z = sigf(v0.z); a.w = sigf(v0.w);
        if (m){
            float4 v1 = __ldcs(&vl4[r1 + f]);
            a.x = (a.x + sigf(v1.x)) * 0.5f;
            a.y = (a.y + sigf(v1.y)) * 0.5f;
            a.z = (a.z + sigf(v1.z)) * 0.5f;
            a.w = (a.w + sigf(v1.w)) * 0.5f;
        }
        g_a1[(size_t)q*NN4 + f] = pack4h(a.x, a.y, a.z, a.w);
        unsigned nib = (unsigned)(a.x > 0.5f) | ((unsigned)(a.y > 0.5f) << 1)
                     | ((unsigned)(a.z > 0.5f) << 2) | ((unsigned)(a.w > 0.5f) << 3);
        unsigned part = nib << ((lane & 7) * 4);
        part |= __shfl_xor_sync(~0u, part, 1);
        part |= __shfl_xor_sync(~0u, part, 2);
        part |= __shfl_xor_sync(~0u, part, 4);
        if ((lane & 7) == 0) g_mask2[(size_t)q*NW + (f >> 3)] = part;
    }
}

// ---------------- pass 3: final output (sig2 fp16 instead of logits) ----------------
__global__ void out_kernel(float4* __restrict__ out4){
    int q = blockIdx.y;
    int t = threadIdx.x;
    size_t orow4 = (size_t)q * NN4;
    int keep = g_keep[q];
    int m2 = g_m2[q];
    const uint2* s2p = g_sig2 + (size_t)g_idx2[q] * NN4;
    #pragma unroll
    for (int j = 0; j < 4; j++){
        int f = blockIdx.x*1024 + j*256 + t;
        float4 o = make_float4(0.f, 0.f, 0.f, 0.f);
        if (keep){
            float4 a = unpack4h(g_a1[(size_t)q*NN4 + f]);   // mostly L2-hit
            if (m2){
                float4 s2 = unpack4h(__ldcs(&s2p[f]));
                a.x = (a.x*2.f + s2.x) * (1.f/3.f);
                a.y = (a.y*2.f + s2.y) * (1.f/3.f);
                a.z = (a.z*2.f + s2.z) * (1.f/3.f);
                a.w = (a.w*2.f + s2.w) * (1.f/3.f);
            }
            unsigned ob = g_occ[f >> 3] >> ((f & 7) * 4);
            o.x = (ob & 1u) ? a.x : 0.f;
            o.y = (ob & 2u) ? a.y : 0.f;
            o.z = (ob & 4u) ? a.z : 0.f;
            o.w = (ob & 8u) ? a.w : 0.f;
        }
        __stcs(&out4[orow4 + f], o);
    }
}

// ---------------- launch: R11 schedule, sig2-cached out ----------------
extern "C" void kernel_launch(void* const* d_in, const int* in_sizes, int n_in,
                              void* d_out, int out_size){
    const float4* vl4  = (const float4*)d_in[0];   // voxel_logits [3,64,128,128,32]
    const float4* sem4 = (const float4*)d_in[2];   // sem_prob_dense [21,128,128,32]
    float4* out4 = (float4*)d_out;                 // [64,128,128,32]

    static cudaStream_t s1 = 0;
    static cudaEvent_t evA = 0, evI0 = 0, evM2 = 0, evI1 = 0;
    static int initd = 0;
    if (!initd){
        if (cudaStreamCreateWithFlags(&s1, cudaStreamNonBlocking) != cudaSuccess) s1 = 0;
        cudaEventCreateWithFlags(&evA,  cudaEventDisableTiming);
        cudaEventCreateWithFlags(&evI0, cudaEventDisableTiming);
        cudaEventCreateWithFlags(&evM2, cudaEventDisableTiming);
        cudaEventCreateWithFlags(&evI1, cudaEventDisableTiming);
        initd = 1;
    }

    init_kernel <<< 16, 256 >>> ();

    if (s1){
        // S0: mask01 (s=0,1) — inter0's inputs
        mask_kernel <<< dim3(NN4/1024, NQ, 2), 256 >>> (vl4);
        cudaEventRecord(evA, 0);

        // S1: inter0 runs concurrent with S0's mask_s2
        cudaStreamWaitEvent(s1, evA, 0);
        inter_kernel<<< dim3(NW/WCH, 4, 4), 256, 0, s1 >>> (0);
        cudaEventRecord(evI0, s1);

        // S0: mask s=2 + sig2 fp16 (DRAM work under inter0's ALU window)
        mask_s2_kernel <<< dim3(NN4/1024, NQ), 256 >>> (vl4);

        // S0: match0 -> mask2
        cudaStreamWaitEvent(0, evI0, 0);
        match_kernel<<< 8, 256 >>> (0);
        mask2_kernel<<< dim3(NN4/1024, NQ), 256 >>> (vl4);
        cudaEventRecord(evM2, 0);

        // S1: inter1 concurrent with S0's occ
        cudaStreamWaitEvent(s1, evM2, 0);
        inter_kernel<<< dim3(NW/WCH, 4, 4), 256, 0, s1 >>> (1);
        cudaEventRecord(evI1, s1);

        // S0: occ (DRAM work under inter1's ALU window)
        occ_kernel  <<< NN4/256, 256 >>> (sem4);

        cudaStreamWaitEvent(0, evI1, 0);
        match_kernel<<< 8, 256 >>> (1);
        out_kernel  <<< dim3(NN4/1024, NQ), 256 >>> (out4);
    } else {
        mask_kernel <<< dim3(NN4/1024, NQ, 2), 256 >>> (vl4);
        mask_s2_kernel <<< dim3(NN4/1024, NQ), 256 >>> (vl4);
        occ_kernel  <<< NN4/256, 256 >>> (sem4);
        inter_kernel<<< dim3(NW/WCH, 4, 4), 256 >>> (0);
        match_kernel<<< 8, 256 >>> (0);
        mask2_kernel<<< dim3(NN4/1024, NQ), 256 >>> (vl4);
        inter_kernel<<< dim3(NW/WCH, 4, 4), 256 >>> (1);
        match_kernel<<< 8, 256 >>> (1);
        out_kernel  <<< dim3(NN4/1024, NQ), 256 >>> (out4);
    }
}

// round 15
// speedup vs baseline: 1.1723x; 1.0994x over previous
#include <cuda_runtime.h>
#include <cuda_fp16.h>

#define NS 3
#define NQ 64
#define NN (128*128*32)    // 524288
#define NN4 (NN/4)         // 131072 float4 per row
#define NW (NN/32)         // 16384 packed words per row
#define NC 21
#define IOU_T 0.2f
#define WCH 256
#define SROW (WCH+4)       // 260-word smem row stride

// ---------------- scratch (device globals; no allocation) ----------------
__device__ unsigned g_mask [NS*NQ*NW];
__device__ unsigned g_mask2[NQ*NW];
__device__ unsigned g_occ  [NW];
__device__ uint2    g_a1   [(size_t)NQ*NN4];   // merged anchor after iter1, fp16x4 (output path only)
__device__ uint2    g_sig2 [(size_t)NQ*NN4];   // sigmoid(l2), fp16x4 (output path only)
__device__ int g_cnt [NS*NQ];
__device__ int g_cnt2[NQ];
__device__ int g_inter1[NQ*NQ];
__device__ int g_inter2[NQ*NQ];
__device__ int g_idx1[NQ], g_m1[NQ], g_idx2[NQ], g_m2[NQ], g_keep[NQ];
__device__ float g_iou1[NQ];

// fast sigmoid: MUFU.EX2 + MUFU.RCP (error ~1e-7, same regime as __expf itself)
__device__ __forceinline__ float sigf(float x){
    return __fdividef(1.0f, 1.0f + __expf(-x));
}

__device__ __forceinline__ uint2 pack4h(float a, float b, float c, float d){
    __half2 h01 = __floats2half2_rn(a, b);
    __half2 h23 = __floats2half2_rn(c, d);
    uint2 r; r.x = *(unsigned*)&h01; r.y = *(unsigned*)&h23; return r;
}
__device__ __forceinline__ float4 unpack4h(uint2 hv){
    float2 a01 = __half22float2(*(__half2*)&hv.x);
    float2 a23 = __half22float2(*(__half2*)&hv.y);
    return make_float4(a01.x, a01.y, a23.x, a23.y);
}

// ---------------- zero accumulators ----------------
__global__ void init_kernel(){
    int t = blockIdx.x*256 + threadIdx.x;
    if (t < NQ*NQ){ g_inter1[t] = 0; g_inter2[t] = 0; }
    if (t < NS*NQ) g_cnt[t] = 0;
    if (t < NQ)    g_cnt2[t] = 0;
}

// ---------------- occupancy bits (pure streaming) ----------------
__global__ void occ_kernel(const float4* __restrict__ sem4){
    int f = blockIdx.x*256 + threadIdx.x;
    int lane = threadIdx.x & 31;
    float4 v0 = __ldcs(&sem4[f]);
    unsigned nib = 0;
    #pragma unroll
    for (int c = 1; c < NC; c++){
        float4 vc = __ldcs(&sem4[(size_t)c*NN4 + f]);
        nib |= (unsigned)(vc.x > v0.x) | ((unsigned)(vc.y > v0.y) << 1)
             | ((unsigned)(vc.z > v0.z) << 2) | ((unsigned)(vc.w > v0.w) << 3);
    }
    unsigned part = nib << ((lane & 7) * 4);
    part |= __shfl_xor_sync(~0u, part, 1);
    part |= __shfl_xor_sync(~0u, part, 2);
    part |= __shfl_xor_sync(~0u, part, 4);
    if ((lane & 7) == 0) g_occ[f >> 3] = part;
}

// ---------------- pass 1: pack (logit>0) bits, s=0,1 — pure stream ----------------
__global__ void mask_kernel(const float4* __restrict__ vl4){
    int s = blockIdx.z, q = blockIdx.y;
    int row = s*NQ + q;
    size_t row4 = (size_t)row * NN4;
    size_t mrow = (size_t)row * NW;
    int t = threadIdx.x, lane = t & 31;
    #pragma unroll
    for (int j = 0; j < 4; j++){
        int f = blockIdx.x*1024 + j*256 + t;
        float4 v = __ldcs(&vl4[row4 + f]);
        unsigned nib = (unsigned)(v.x > 0.f) | ((unsigned)(v.y > 0.f) << 1)
                     | ((unsigned)(v.z > 0.f) << 2) | ((unsigned)(v.w > 0.f) << 3);
        unsigned part = nib << ((lane & 7) * 4);
        part |= __shfl_xor_sync(~0u, part, 1);
        part |= __shfl_xor_sync(~0u, part, 2);
        part |= __shfl_xor_sync(~0u, part, 4);
        if ((lane & 7) == 0) g_mask[mrow + (f >> 3)] = part;
    }
}

// ---------------- pass 1b (s=2): bits + sigmoid(l2) fp16 cache ----------------
__global__ void mask_s2_kernel(const float4* __restrict__ vl4){
    int q = blockIdx.y;
    int row = 2*NQ + q;
    size_t row4 = (size_t)row * NN4;
    size_t mrow = (size_t)row * NW;
    int t = threadIdx.x, lane = t & 31;
    #pragma unroll
    for (int j = 0; j < 4; j++){
        int f = blockIdx.x*1024 + j*256 + t;
        float4 v = __ldcs(&vl4[row4 + f]);
        g_sig2[(size_t)q*NN4 + f] = pack4h(sigf(v.x), sigf(v.y), sigf(v.z), sigf(v.w));
        unsigned nib = (unsigned)(v.x > 0.f) | ((unsigned)(v.y > 0.f) << 1)
                     | ((unsigned)(v.z > 0.f) << 2) | ((unsigned)(v.w > 0.f) << 3);
        unsigned part = nib << ((lane & 7) * 4);
        part |= __shfl_xor_sync(~0u, part, 1);
        part |= __shfl_xor_sync(~0u, part, 2);
        part |= __shfl_xor_sync(~0u, part, 4);
        if ((lane & 7) == 0) g_mask[mrow + (f >> 3)] = part;
    }
}

// ---------------- bit-popcount GEMM + fused row counts (R6 body; 3 blocks/SM) ----------------
__global__ void __launch_bounds__(256, 3) inter_kernel(int round){
    __shared__ unsigned sA[16*SROW];
    __shared__ unsigned sB[16*SROW];
    const unsigned* A = round ? g_mask2 : g_mask;
    const unsigned* B = g_mask + (size_t)(round ? 2 : 1) * NQ * NW;
    int* inter = round ? g_inter2 : g_inter1;
    int* cntA  = round ? g_cnt2 : g_cnt;
    int* cntB  = g_cnt + (round ? 2 : 1) * NQ;
    int w0 = blockIdx.x * WCH;
    int q0 = blockIdx.y * 16, p0 = blockIdx.z * 16;
    int t = threadIdx.x;
    for (int i = t; i < 16*64; i += 256){
        int r = i >> 6, c = (i & 63) * 4;
        *(uint4*)&sA[r*SROW + c] = *(const uint4*)&A[(size_t)(q0 + r)*NW + w0 + c];
        *(uint4*)&sB[r*SROW + c] = *(const uint4*)&B[(size_t)(p0 + r)*NW + w0 + c];
    }
    __syncthreads();
    if (blockIdx.z == 0){
        int r = t >> 4, part = t & 15;
        int c = 0;
        #pragma unroll
        for (int w = 0; w < 16; w++) c += __popc(sA[r*SROW + part*16 + w]);
        #pragma unroll
        for (int d = 8; d; d >>= 1) c += __shfl_down_sync(~0u, c, d, 16);
        if (part == 0) atomicAdd(&cntA[q0 + r], c);
    }
    if (blockIdx.y == 0){
        int r = t >> 4, part = t & 15;
        int c = 0;
        #pragma unroll
        for (int w = 0; w < 16; w++) c += __popc(sB[r*SROW + part*16 + w]);
        #pragma unroll
        for (int d = 8; d; d >>= 1) c += __shfl_down_sync(~0u, c, d, 16);
        if (part == 0) atomicAdd(&cntB[p0 + r], c);
    }
    int px = t & 3, qx = (t >> 2) & 3, ws = t >> 4;
    int acc[16];
    #pragma unroll
    for (int k = 0; k < 16; k++) acc[k] = 0;
    int wbeg = ws * 16;
    #pragma unroll
    for (int w = wbeg; w < wbeg + 16; w += 4){
        uint4 a[4], b[4];
        #pragma unroll
        for (int i = 0; i < 4; i++){
            a[i] = *(uint4*)&sA[(qx + 4*i)*SROW + w];
            b[i] = *(uint4*)&sB[(px + 4*i)*SROW + w];
        }
        #pragma unroll
        for (int i = 0; i < 4; i++)
            #pragma unroll
            for (int j = 0; j < 4; j++)
                acc[i*4+j] += __popc(a[i].x & b[j].x) + __popc(a[i].y & b[j].y)
                            + __popc(a[i].z & b[j].z) + __popc(a[i].w & b[j].w);
    }
    __syncthreads();
    int* sRed = (int*)sA;
    #pragma unroll
    for (int i = 0; i < 4; i++)
        #pragma unroll
        for (int j = 0; j < 4; j++)
            sRed[ws*256 + (qx + 4*i)*16 + (px + 4*j)] = acc[i*4+j];
    __syncthreads();
    int s = 0;
    #pragma unroll
    for (int k = 0; k < 16; k++) s += sRed[k*256 + t];
    atomicAdd(&inter[(q0 + (t >> 4))*NQ + p0 + (t & 15)], s);
}

// ---------------- parallel argmax: one warp per q (first-index tie-break) ----------------
__global__ void match_kernel(int round){
    int q = blockIdx.x*8 + (threadIdx.x >> 5);
    int lane = threadIdx.x & 31;
    const int* inter = round ? g_inter2 : g_inter1;
    const int* cb    = g_cnt + (round ? 2*NQ : NQ);
    float ca = (float)(round ? g_cnt2[q] : g_cnt[q]);
    float best = -1.0f; int bi = 0;
    #pragma unroll
    for (int k = 0; k < 2; k++){
        int p = lane + k*32;
        float in = (float)inter[q*NQ + p];
        float un = ca + (float)cb[p] - in;
        float io = in / fmaxf(un, 1.0f);
        if (io > best){ best = io; bi = p; }
    }
    #pragma unroll
    for (int d = 16; d; d >>= 1){
        float ob = __shfl_xor_sync(~0u, best, d);
        int   oi = __shfl_xor_sync(~0u, bi,   d);
        if (ob > best || (ob == best && oi < bi)){ best = ob; bi = oi; }
    }
    if (lane == 0){
        if (round == 0){
            g_idx1[q] = bi; g_m1[q] = best > IOU_T; g_iou1[q] = best;
        } else {
            g_idx2[q] = bi; g_m2[q] = best > IOU_T;
            g_keep[q] = ((g_iou1[q] + best) * 0.5f) > IOU_T;
        }
    }
}

// ---------------- pass 2: merged anchor bits + fp16 a1 ----------------
__global__ void mask2_kernel(const float4* __restrict__ vl4){
    int q = blockIdx.y;
    int t = threadIdx.x, lane = t & 31;
    int p = g_idx1[q], m = g_m1[q];
    size_t r0 = (size_t)q * NN4;
    size_t r1 = (size_t)(NQ + p) * NN4;
    #pragma unroll
    for (int j = 0; j < 4; j++){
        int f = blockIdx.x*1024 + j*256 + t;
        float4 v0 = __ldcs(&vl4[r0 + f]);
        float4 a;
        a.x = sigf(v0.x); a.y = sigf(v0.y); a.z = sigf(v0.z); a.w = sigf(v0.w);
        if (m){
            float4 v1 = __ldcs(&vl4[r1 + f]);
            a.x = (a.x + sigf(v1.x)) * 0.5f;
            a.y = (a.y + sigf(v1.y)) * 0.5f;
            a.z = (a.z + sigf(v1.z)) * 0.5f;
            a.w = (a.w + sigf(v1.w)) * 0.5f;
        }
        g_a1[(size_t)q*NN4 + f] = pack4h(a.x, a.y, a.z, a.w);
        unsigned nib = (unsigned)(a.x > 0.5f) | ((unsigned)(a.y > 0.5f) << 1)
                     | ((unsigned)(a.z > 0.5f) << 2) | ((unsigned)(a.w > 0.5f) << 3);
        unsigned part = nib << ((lane & 7) * 4);
        part |= __shfl_xor_sync(~0u, part, 1);
        part |= __shfl_xor_sync(~0u, part, 2);
        part |= __shfl_xor_sync(~0u, part, 4);
        if ((lane & 7) == 0) g_mask2[(size_t)q*NW + (f >> 3)] = part;
    }
}

// ---------------- pass 3: final output (sig2 fp16 instead of logits) ----------------
__global__ void out_kernel(float4* __restrict__ out4){
    int q = blockIdx.y;
    int t = threadIdx.x;
    size_t orow4 = (size_t)q * NN4;
    int keep = g_keep[q];
    int m2 = g_m2[q];
    const uint2* s2p = g_sig2 + (size_t)g_idx2[q] * NN4;
    #pragma unroll
    for (int j = 0; j < 4; j++){
        int f = blockIdx.x*1024 + j*256 + t;
        float4 o = make_float4(0.f, 0.f, 0.f, 0.f);
        if (keep){
            float4 a = unpack4h(g_a1[(size_t)q*NN4 + f]);   // mostly L2-hit
            if (m2){
                float4 s2 = unpack4h(__ldcs(&s2p[f]));
                a.x = (a.x*2.f + s2.x) * (1.f/3.f);
                a.y = (a.y*2.f + s2.y) * (1.f/3.f);
                a.z = (a.z*2.f + s2.z) * (1.f/3.f);
                a.w = (a.w*2.f + s2.w) * (1.f/3.f);
            }
            unsigned ob = g_occ[f >> 3] >> ((f & 7) * 4);
            o.x = (ob & 1u) ? a.x : 0.f;
            o.y = (ob & 2u) ? a.y : 0.f;
            o.z = (ob & 4u) ? a.z : 0.f;
            o.w = (ob & 8u) ? a.w : 0.f;
        }
        __stcs(&out4[orow4 + f], o);
    }
}

// ---------------- launch: R11/R14 schedule ----------------
extern "C" void kernel_launch(void* const* d_in, const int* in_sizes, int n_in,
                              void* d_out, int out_size){
    const float4* vl4  = (const float4*)d_in[0];   // voxel_logits [3,64,128,128,32]
    const float4* sem4 = (const float4*)d_in[2];   // sem_prob_dense [21,128,128,32]
    float4* out4 = (float4*)d_out;                 // [64,128,128,32]

    static cudaStream_t s1 = 0;
    static cudaEvent_t evA = 0, evI0 = 0, evM2 = 0, evI1 = 0;
    static int initd = 0;
    if (!initd){
        if (cudaStreamCreateWithFlags(&s1, cudaStreamNonBlocking) != cudaSuccess) s1 = 0;
        cudaEventCreateWithFlags(&evA,  cudaEventDisableTiming);
        cudaEventCreateWithFlags(&evI0, cudaEventDisableTiming);
        cudaEventCreateWithFlags(&evM2, cudaEventDisableTiming);
        cudaEventCreateWithFlags(&evI1, cudaEventDisableTiming);
        initd = 1;
    }

    init_kernel <<< 16, 256 >>> ();

    if (s1){
        // S0: mask01 (s=0,1) — inter0's inputs
        mask_kernel <<< dim3(NN4/1024, NQ, 2), 256 >>> (vl4);
        cudaEventRecord(evA, 0);

        // S1: inter0 runs concurrent with S0's mask_s2
        cudaStreamWaitEvent(s1, evA, 0);
        inter_kernel<<< dim3(NW/WCH, 4, 4), 256, 0, s1 >>> (0);
        cudaEventRecord(evI0, s1);

        // S0: mask s=2 + sig2 fp16 (DRAM work under inter0's ALU window)
        mask_s2_kernel <<< dim3(NN4/1024, NQ), 256 >>> (vl4);

        // S0: match0 -> mask2
        cudaStreamWaitEvent(0, evI0, 0);
        match_kernel<<< 8, 256 >>> (0);
        mask2_kernel<<< dim3(NN4/1024, NQ), 256 >>> (vl4);
        cudaEventRecord(evM2, 0);

        // S1: inter1 concurrent with S0's occ
        cudaStreamWaitEvent(s1, evM2, 0);
        inter_kernel<<< dim3(NW/WCH, 4, 4), 256, 0, s1 >>> (1);
        cudaEventRecord(evI1, s1);

        // S0: occ (DRAM work under inter1's ALU window)
        occ_kernel  <<< NN4/256, 256 >>> (sem4);

        cudaStreamWaitEvent(0, evI1, 0);
        match_kernel<<< 8, 256 >>> (1);
        out_kernel  <<< dim3(NN4/1024, NQ), 256 >>> (out4);
    } else {
        mask_kernel <<< dim3(NN4/1024, NQ, 2), 256 >>> (vl4);
        mask_s2_kernel <<< dim3(NN4/1024, NQ), 256 >>> (vl4);
        occ_kernel  <<< NN4/256, 256 >>> (sem4);
        inter_kernel<<< dim3(NW/WCH, 4, 4), 256 >>> (0);
        match_kernel<<< 8, 256 >>> (0);
        mask2_kernel<<< dim3(NN4/1024, NQ), 256 >>> (vl4);
        inter_kernel<<< dim3(NW/WCH, 4, 4), 256 >>> (1);
        match_kernel<<< 8, 256 >>> (1);
        out_kernel  <<< dim3(NN4/1024, NQ), 256 >>> (out4);
    }
}

// round 16
// speedup vs baseline: 1.1753x; 1.0026x over previous
#include <cuda_runtime.h>
#include <cuda_fp16.h>

#define NS 3
#define NQ 64
#define NN (128*128*32)    // 524288
#define NN4 (NN/4)         // 131072 float4 per row
#define NW (NN/32)         // 16384 packed words per row
#define NC 21
#define IOU_T 0.2f
#define WCH 256
#define SROW (WCH+4)       // 260-word smem row stride

// ---------------- scratch (device globals; no allocation) ----------------
__device__ unsigned g_mask [NS*NQ*NW];
__device__ unsigned g_mask2[NQ*NW];
__device__ unsigned g_occ  [NW];
__device__ uint2    g_a1   [(size_t)NQ*NN4];   // merged anchor after iter1, fp16x4 (output path only)
__device__ uint2    g_sig2 [(size_t)NQ*NN4];   // sigmoid(l2), fp16x4 (output path only)
__device__ int g_cnt [NS*NQ];
__device__ int g_cnt2[NQ];
__device__ int g_inter1[NQ*NQ];
__device__ int g_inter2[NQ*NQ];
__device__ int g_idx1[NQ], g_m1[NQ], g_idx2[NQ], g_m2[NQ], g_keep[NQ];
__device__ float g_iou1[NQ];

// fast sigmoid: MUFU.EX2 + MUFU.RCP (error ~1e-7, same regime as __expf itself)
__device__ __forceinline__ float sigf(float x){
    return __fdividef(1.0f, 1.0f + __expf(-x));
}

__device__ __forceinline__ uint2 pack4h(float a, float b, float c, float d){
    __half2 h01 = __floats2half2_rn(a, b);
    __half2 h23 = __floats2half2_rn(c, d);
    uint2 r; r.x = *(unsigned*)&h01; r.y = *(unsigned*)&h23; return r;
}
__device__ __forceinline__ float4 unpack4h(uint2 hv){
    float2 a01 = __half22float2(*(__half2*)&hv.x);
    float2 a23 = __half22float2(*(__half2*)&hv.y);
    return make_float4(a01.x, a01.y, a23.x, a23.y);
}

// ---------------- zero accumulators ----------------
__global__ void init_kernel(){
    int t = blockIdx.x*256 + threadIdx.x;
    if (t < NQ*NQ){ g_inter1[t] = 0; g_inter2[t] = 0; }
    if (t < NS*NQ) g_cnt[t] = 0;
    if (t < NQ)    g_cnt2[t] = 0;
}

// ---------------- occupancy bits (pure streaming) ----------------
__global__ void occ_kernel(const float4* __restrict__ sem4){
    int f = blockIdx.x*256 + threadIdx.x;
    int lane = threadIdx.x & 31;
    float4 v0 = __ldcs(&sem4[f]);
    unsigned nib = 0;
    #pragma unroll
    for (int c = 1; c < NC; c++){
        float4 vc = __ldcs(&sem4[(size_t)c*NN4 + f]);
        nib |= (unsigned)(vc.x > v0.x) | ((unsigned)(vc.y > v0.y) << 1)
             | ((unsigned)(vc.z > v0.z) << 2) | ((unsigned)(vc.w > v0.w) << 3);
    }
    unsigned part = nib << ((lane & 7) * 4);
    part |= __shfl_xor_sync(~0u, part, 1);
    part |= __shfl_xor_sync(~0u, part, 2);
    part |= __shfl_xor_sync(~0u, part, 4);
    if ((lane & 7) == 0) g_occ[f >> 3] = part;
}

// ---------------- pass 1: pack (logit>0) bits, s=0,1 — pure stream ----------------
__global__ void mask_kernel(const float4* __restrict__ vl4){
    int s = blockIdx.z, q = blockIdx.y;
    int row = s*NQ + q;
    size_t row4 = (size_t)row * NN4;
    size_t mrow = (size_t)row * NW;
    int t = threadIdx.x, lane = t & 31;
    #pragma unroll
    for (int j = 0; j < 4; j++){
        int f = blockIdx.x*1024 + j*256 + t;
        float4 v = __ldcs(&vl4[row4 + f]);
        unsigned nib = (unsigned)(v.x > 0.f) | ((unsigned)(v.y > 0.f) << 1)
                     | ((unsigned)(v.z > 0.f) << 2) | ((unsigned)(v.w > 0.f) << 3);
        unsigned part = nib << ((lane & 7) * 4);
        part |= __shfl_xor_sync(~0u, part, 1);
        part |= __shfl_xor_sync(~0u, part, 2);
        part |= __shfl_xor_sync(~0u, part, 4);
        if ((lane & 7) == 0) g_mask[mrow + (f >> 3)] = part;
    }
}

// ---------------- pass 1b (s=2): bits + sigmoid(l2) fp16 cache ----------------
__global__ void mask_s2_kernel(const float4* __restrict__ vl4){
    int q = blockIdx.y;
    int row = 2*NQ + q;
    size_t row4 = (size_t)row * NN4;
    size_t mrow = (size_t)row * NW;
    int t = threadIdx.x, lane = t & 31;
    #pragma unroll
    for (int j = 0; j < 4; j++){
        int f = blockIdx.x*1024 + j*256 + t;
        float4 v = __ldcs(&vl4[row4 + f]);
        g_sig2[(size_t)q*NN4 + f] = pack4h(sigf(v.x), sigf(v.y), sigf(v.z), sigf(v.w));
        unsigned nib = (unsigned)(v.x > 0.f) | ((unsigned)(v.y > 0.f) << 1)
                     | ((unsigned)(v.z > 0.f) << 2) | ((unsigned)(v.w > 0.f) << 3);
        unsigned part = nib << ((lane & 7) * 4);
        part |= __shfl_xor_sync(~0u, part, 1);
        part |= __shfl_xor_sync(~0u, part, 2);
        part |= __shfl_xor_sync(~0u, part, 4);
        if ((lane & 7) == 0) g_mask[mrow + (f >> 3)] = part;
    }
}

// ---------------- bit-popcount GEMM + fused row counts (R6 body; 3 blocks/SM) ----------------
__global__ void __launch_bounds__(256, 3) inter_kernel(int round){
    __shared__ unsigned sA[16*SROW];
    __shared__ unsigned sB[16*SROW];
    const unsigned* A = round ? g_mask2 : g_mask;
    const unsigned* B = g_mask + (size_t)(round ? 2 : 1) * NQ * NW;
    int* inter = round ? g_inter2 : g_inter1;
    int* cntA  = round ? g_cnt2 : g_cnt;
    int* cntB  = g_cnt + (round ? 2 : 1) * NQ;
    int w0 = blockIdx.x * WCH;
    int q0 = blockIdx.y * 16, p0 = blockIdx.z * 16;
    int t = threadIdx.x;
    for (int i = t; i < 16*64; i += 256){
        int r = i >> 6, c = (i & 63) * 4;
        *(uint4*)&sA[r*SROW + c] = *(const uint4*)&A[(size_t)(q0 + r)*NW + w0 + c];
        *(uint4*)&sB[r*SROW + c] = *(const uint4*)&B[(size_t)(p0 + r)*NW + w0 + c];
    }
    __syncthreads();
    if (blockIdx.z == 0){
        int r = t >> 4, part = t & 15;
        int c = 0;
        #pragma unroll
        for (int w = 0; w < 16; w++) c += __popc(sA[r*SROW + part*16 + w]);
        #pragma unroll
        for (int d = 8; d; d >>= 1) c += __shfl_down_sync(~0u, c, d, 16);
        if (part == 0) atomicAdd(&cntA[q0 + r], c);
    }
    if (blockIdx.y == 0){
        int r = t >> 4, part = t & 15;
        int c = 0;
        #pragma unroll
        for (int w = 0; w < 16; w++) c += __popc(sB[r*SROW + part*16 + w]);
        #pragma unroll
        for (int d = 8; d; d >>= 1) c += __shfl_down_sync(~0u, c, d, 16);
        if (part == 0) atomicAdd(&cntB[p0 + r], c);
    }
    int px = t & 3, qx = (t >> 2) & 3, ws = t >> 4;
    int acc[16];
    #pragma unroll
    for (int k = 0; k < 16; k++) acc[k] = 0;
    int wbeg = ws * 16;
    #pragma unroll
    for (int w = wbeg; w < wbeg + 16; w += 4){
        uint4 a[4], b[4];
        #pragma unroll
        for (int i = 0; i < 4; i++){
            a[i] = *(uint4*)&sA[(qx + 4*i)*SROW + w];
            b[i] = *(uint4*)&sB[(px + 4*i)*SROW + w];
        }
        #pragma unroll
        for (int i = 0; i < 4; i++)
            #pragma unroll
            for (int j = 0; j < 4; j++)
                acc[i*4+j] += __popc(a[i].x & b[j].x) + __popc(a[i].y & b[j].y)
                            + __popc(a[i].z & b[j].z) + __popc(a[i].w & b[j].w);
    }
    __syncthreads();
    int* sRed = (int*)sA;
    #pragma unroll
    for (int i = 0; i < 4; i++)
        #pragma unroll
        for (int j = 0; j < 4; j++)
            sRed[ws*256 + (qx + 4*i)*16 + (px + 4*j)] = acc[i*4+j];
    __syncthreads();
    int s = 0;
    #pragma unroll
    for (int k = 0; k < 16; k++) s += sRed[k*256 + t];
    atomicAdd(&inter[(q0 + (t >> 4))*NQ + p0 + (t & 15)], s);
}

// ---------------- parallel argmax: one warp per q (first-index tie-break) ----------------
__global__ void match_kernel(int round){
    int q = blockIdx.x*8 + (threadIdx.x >> 5);
    int lane = threadIdx.x & 31;
    const int* inter = round ? g_inter2 : g_inter1;
    const int* cb    = g_cnt + (round ? 2*NQ : NQ);
    float ca = (float)(round ? g_cnt2[q] : g_cnt[q]);
    float best = -1.0f; int bi = 0;
    #pragma unroll
    for (int k = 0; k < 2; k++){
        int p = lane + k*32;
        float in = (float)inter[q*NQ + p];
        float un = ca + (float)cb[p] - in;
        float io = in / fmaxf(un, 1.0f);
        if (io > best){ best = io; bi = p; }
    }
    #pragma unroll
    for (int d = 16; d; d >>= 1){
        float ob = __shfl_xor_sync(~0u, best, d);
        int   oi = __shfl_xor_sync(~0u, bi,   d);
        if (ob > best || (ob == best && oi < bi)){ best = ob; bi = oi; }
    }
    if (lane == 0){
        if (round == 0){
            g_idx1[q] = bi; g_m1[q] = best > IOU_T; g_iou1[q] = best;
        } else {
            g_idx2[q] = bi; g_m2[q] = best > IOU_T;
            g_keep[q] = ((g_iou1[q] + best) * 0.5f) > IOU_T;
        }
    }
}

// ---------------- pass 2: merged anchor bits + fp16 a1 ----------------
__global__ void mask2_kernel(const float4* __restrict__ vl4){
    int q = blockIdx.y;
    int t = threadIdx.x, lane = t & 31;
    int p = g_idx1[q], m = g_m1[q];
    size_t r0 = (size_t)q * NN4;
    size_t r1 = (size_t)(NQ + p) * NN4;
    #pragma unroll
    for (int j = 0; j < 4; j++){
        int f = blockIdx.x*1024 + j*256 + t;
        float4 v0 = __ldcs(&vl4[r0 + f]);
        float4 a;
        a.x = sigf(v0.x); a.y = sigf(v0.y); a.z = sigf(v0.z); a.w = sigf(v0.w);
        if (m){
            float4 v1 = __ldcs(&vl4[r1 + f]);
            a.x = (a.x + sigf(v1.x)) * 0.5f;
            a.y = (a.y + sigf(v1.y)) * 0.5f;
            a.z = (a.z + sigf(v1.z)) * 0.5f;
            a.w = (a.w + sigf(v1.w)) * 0.5f;
        }
        g_a1[(size_t)q*NN4 + f] = pack4h(a.x, a.y, a.z, a.w);
        unsigned nib = (unsigned)(a.x > 0.5f) | ((unsigned)(a.y > 0.5f) << 1)
                     | ((unsigned)(a.z > 0.5f) << 2) | ((unsigned)(a.w > 0.5f) << 3);
        unsigned part = nib << ((lane & 7) * 4);
        part |= __shfl_xor_sync(~0u, part, 1);
        part |= __shfl_xor_sync(~0u, part, 2);
        part |= __shfl_xor_sync(~0u, part, 4);
        if ((lane & 7) == 0) g_mask2[(size_t)q*NW + (f >> 3)] = part;
    }
}

// ---------------- pass 3: final output (sig2 fp16 instead of logits) ----------------
__global__ void out_kernel(float4* __restrict__ out4){
    int q = blockIdx.y;
    int t = threadIdx.x;
    size_t orow4 = (size_t)q * NN4;
    int keep = g_keep[q];
    int m2 = g_m2[q];
    const uint2* s2p = g_sig2 + (size_t)g_idx2[q] * NN4;
    #pragma unroll
    for (int j = 0; j < 4; j++){
        int f = blockIdx.x*1024 + j*256 + t;
        float4 o = make_float4(0.f, 0.f, 0.f, 0.f);
        if (keep){
            float4 a = unpack4h(g_a1[(size_t)q*NN4 + f]);   // mostly L2-hit
            if (m2){
                float4 s2 = unpack4h(__ldcs(&s2p[f]));
                a.x = (a.x*2.f + s2.x) * (1.f/3.f);
                a.y = (a.y*2.f + s2.y) * (1.f/3.f);
                a.z = (a.z*2.f + s2.z) * (1.f/3.f);
                a.w = (a.w*2.f + s2.w) * (1.f/3.f);
            }
            unsigned ob = g_occ[f >> 3] >> ((f & 7) * 4);
            o.x = (ob & 1u) ? a.x : 0.f;
            o.y = (ob & 2u) ? a.y : 0.f;
            o.z = (ob & 4u) ? a.z : 0.f;
            o.w = (ob & 8u) ? a.w : 0.f;
        }
        __stcs(&out4[orow4 + f], o);
    }
}

// ---------------- launch: R11/R14 schedule ----------------
extern "C" void kernel_launch(void* const* d_in, const int* in_sizes, int n_in,
                              void* d_out, int out_size){
    const float4* vl4  = (const float4*)d_in[0];   // voxel_logits [3,64,128,128,32]
    const float4* sem4 = (const float4*)d_in[2];   // sem_prob_dense [21,128,128,32]
    float4* out4 = (float4*)d_out;                 // [64,128,128,32]

    static cudaStream_t s1 = 0;
    static cudaEvent_t evA = 0, evI0 = 0, evM2 = 0, evI1 = 0;
    static int initd = 0;
    if (!initd){
        if (cudaStreamCreateWithFlags(&s1, cudaStreamNonBlocking) != cudaSuccess) s1 = 0;
        cudaEventCreateWithFlags(&evA,  cudaEventDisableTiming);
        cudaEventCreateWithFlags(&evI0, cudaEventDisableTiming);
        cudaEventCreateWithFlags(&evM2, cudaEventDisableTiming);
        cudaEventCreateWithFlags(&evI1, cudaEventDisableTiming);
        initd = 1;
    }

    init_kernel <<< 16, 256 >>> ();

    if (s1){
        // S0: mask01 (s=0,1) — inter0's inputs
        mask_kernel <<< dim3(NN4/1024, NQ, 2), 256 >>> (vl4);
        cudaEventRecord(evA, 0);

        // S1: inter0 runs concurrent with S0's mask_s2
        cudaStreamWaitEvent(s1, evA, 0);
        inter_kernel<<< dim3(NW/WCH, 4, 4), 256, 0, s1 >>> (0);
        cudaEventRecord(evI0, s1);

        // S0: mask s=2 + sig2 fp16 (DRAM work under inter0's ALU window)
        mask_s2_kernel <<< dim3(NN4/1024, NQ), 256 >>> (vl4);

        // S0: match0 -> mask2
        cudaStreamWaitEvent(0, evI0, 0);
        match_kernel<<< 8, 256 >>> (0);
        mask2_kernel<<< dim3(NN4/1024, NQ), 256 >>> (vl4);
        cudaEventRecord(evM2, 0);

        // S1: inter1 concurrent with S0's occ
        cudaStreamWaitEvent(s1, evM2, 0);
        inter_kernel<<< dim3(NW/WCH, 4, 4), 256, 0, s1 >>> (1);
        cudaEventRecord(evI1, s1);

        // S0: occ (DRAM work under inter1's ALU window)
        occ_kernel  <<< NN4/256, 256 >>> (sem4);

        cudaStreamWaitEvent(0, evI1, 0);
        match_kernel<<< 8, 256 >>> (1);
        out_kernel  <<< dim3(NN4/1024, NQ), 256 >>> (out4);
    } else {
        mask_kernel <<< dim3(NN4/1024, NQ, 2), 256 >>> (vl4);
        mask_s2_kernel <<< dim3(NN4/1024, NQ), 256 >>> (vl4);
        occ_kernel  <<< NN4/256, 256 >>> (sem4);
        inter_kernel<<< dim3(NW/WCH, 4, 4), 256 >>> (0);
        match_kernel<<< 8, 256 >>> (0);
        mask2_kernel<<< dim3(NN4/1024, NQ), 256 >>> (vl4);
        inter_kernel<<< dim3(NW/WCH, 4, 4), 256 >>> (1);
        match_kernel<<< 8, 256 >>> (1);
        out_kernel  <<< dim3(NN4/1024, NQ), 256 >>> (out4);
    }
}